// round 14
// baseline (speedup 1.0000x reference)
#include <cuda_runtime.h>
#include <cstdint>

// Problem constants
#define NBUCKETS 16
#define EMBD     1024
#define VOCAB    32000
#define SEQLEN   2048
#define RANK     8
#define BATCH    2
#define NTOK     (BATCH * SEQLEN)          // 4096 tokens
#define BUCKET_SHIFT 7                      // SEQLEN / NBUCKETS = 128 = 1<<7

// Scratch for the low-rank projection (alpha folded in): [NTOK][RANK]
__device__ float g_low[NTOK * RANK];

// ---------------------------------------------------------------------------
// Kernel 1 (v6, unchanged from R13): low = alpha * hidden @ A[bucket]
// Register-resident A panel, pure LDG+FFMA main loop, butterfly reduce,
// 4KB smem cross-warp combine.
// ---------------------------------------------------------------------------
#define K1_TOKS 16
#define K1_TPB  256
#define TGRP    4            // tokens per butterfly group

__global__ __launch_bounds__(K1_TPB, 2)
void lowproj_kernel(const float* __restrict__ hidden,
                    const float* __restrict__ A,
                    const float* __restrict__ alpha_p)
{
    __shared__ float part[8][K1_TOKS][RANK];      // 4 KB warp partials

    const int tok0   = blockIdx.x * K1_TOKS;
    const int bucket = (tok0 & (SEQLEN - 1)) >> BUCKET_SHIFT;
    const float* __restrict__ Ab = A + (size_t)bucket * EMBD * RANK;

    const int tid  = threadIdx.x;
    const int wid  = tid >> 5;
    const int lane = tid & 31;
    const int e0   = tid * 4;                     // thread's 4 e-values

    // A panel in registers: af[k*8+r] = A[e0+k][r]
    float4 a[8];
#pragma unroll
    for (int j = 0; j < 8; j++)
        a[j] = *reinterpret_cast<const float4*>(Ab + (size_t)e0 * RANK + j * 4);
    const float* af = reinterpret_cast<const float*>(a);

    const float* __restrict__ hbase = hidden + (size_t)tok0 * EMBD + e0;

#pragma unroll
    for (int grp = 0; grp < K1_TOKS / TGRP; grp++) {
        // Batched hidden loads for 4 tokens (high MLP, coalesced 512B/warp).
        float4 hv[TGRP];
#pragma unroll
        for (int g = 0; g < TGRP; g++)
            hv[g] = __ldcs(reinterpret_cast<const float4*>(
                        hbase + (size_t)(grp * TGRP + g) * EMBD));
        const float* hf = reinterpret_cast<const float*>(hv); // hf[g*4+k]

        // acc index i = g*8 + r
        float v[TGRP * RANK];
#pragma unroll
        for (int i = 0; i < TGRP * RANK; i++) v[i] = 0.0f;

#pragma unroll
        for (int k = 0; k < 4; k++) {
#pragma unroll
            for (int r = 0; r < RANK; r++) {
                const float av = af[k * RANK + r];
#pragma unroll
                for (int g = 0; g < TGRP; g++)
                    v[g * RANK + r] = fmaf(hf[g * 4 + k], av, v[g * RANK + r]);
            }
        }

        // Split-butterfly: 32 values over 32 lanes, 31 shuffles.
#pragma unroll
        for (int m = 16; m >= 1; m >>= 1) {
            const bool hi = (lane & m) != 0;
            const int h = m;
#pragma unroll
            for (int j = 0; j < 16; j++) {
                if (j < h) {
                    float mine   = hi ? v[h + j] : v[j];
                    float theirs = hi ? v[j]     : v[h + j];
                    v[j] = mine + __shfl_xor_sync(0xFFFFFFFFu, theirs, m);
                }
            }
        }

        // One conflict-free 128B line per warp.
        part[wid][grp * TGRP + (lane >> 3)][lane & 7] = v[0];
    }
    __syncthreads();

    // Combine the 8 warps' e-slice partials; 128 threads store 512B coalesced.
    if (tid < K1_TOKS * RANK) {
        const int tok = tid >> 3;
        const int r   = tid & 7;
        float s = 0.0f;
#pragma unroll
        for (int w = 0; w < 8; w++) s += part[w][tok][r];
        g_low[(size_t)(tok0 + tok) * RANK + r] = s * alpha_p[0];
    }
}

// ---------------------------------------------------------------------------
// Kernel 2: out[bt][v] = sum_r low[bt][r] * B[r][v]
// ONLY change this round: plain write-back stores instead of __stcs.
// Theory: evict-first streaming forces eager small writebacks interleaved
// with reads (turnaround cost); write-back lets L2 batch larger DRAM writes
// and raise aggregate achieved bandwidth.
// ---------------------------------------------------------------------------
#define T_TILE 64
#define K2_THREADS 256
#define V4 (VOCAB / 4)        // 8000 float4 per row

__global__ __launch_bounds__(K2_THREADS, 4)
void vocabproj_kernel(const float* __restrict__ B,
                      float* __restrict__ out)
{
    const int v4  = blockIdx.x * K2_THREADS + threadIdx.x;  // float4 column index
    const bool valid = (v4 < V4);
    const int v = v4 * 4;

    // Load B panel into registers: 8 rows x 4 cols
    float4 b[RANK];
#pragma unroll
    for (int r = 0; r < RANK; r++) {
        if (valid)
            b[r] = *reinterpret_cast<const float4*>(B + (size_t)r * VOCAB + v);
        else
            b[r] = make_float4(0.f, 0.f, 0.f, 0.f);
    }

    // Cooperative load of this block's token-tile of low into shared
    __shared__ float slow[T_TILE * RANK];    // 2 KB
    const int tok0 = blockIdx.y * T_TILE;
    for (int i = threadIdx.x; i < T_TILE * RANK / 4; i += K2_THREADS) {
        reinterpret_cast<float4*>(slow)[i] =
            reinterpret_cast<const float4*>(g_low + (size_t)tok0 * RANK)[i];
    }
    __syncthreads();

    if (!valid) return;

    float* __restrict__ op = out + (size_t)tok0 * VOCAB + v;

#pragma unroll 4
    for (int tt = 0; tt < T_TILE; tt++) {
        const float* l = slow + tt * RANK;   // broadcast shared reads
        float4 o;
        o.x = l[0] * b[0].x; o.y = l[0] * b[0].y; o.z = l[0] * b[0].z; o.w = l[0] * b[0].w;
#pragma unroll
        for (int r = 1; r < RANK; r++) {
            o.x = fmaf(l[r], b[r].x, o.x);
            o.y = fmaf(l[r], b[r].y, o.y);
            o.z = fmaf(l[r], b[r].z, o.z);
            o.w = fmaf(l[r], b[r].w, o.w);
        }
        *reinterpret_cast<float4*>(op) = o;   // plain write-back store
        op += VOCAB;
    }
}

// ---------------------------------------------------------------------------
// Launch
// ---------------------------------------------------------------------------
extern "C" void kernel_launch(void* const* d_in, const int* in_sizes, int n_in,
                              void* d_out, int out_size)
{
    const float* hidden = (const float*)d_in[0];   // [2,2048,1024]
    const float* A      = (const float*)d_in[1];   // [16,1024,8]
    const float* B      = (const float*)d_in[2];   // [8,32000]
    const float* alpha  = (const float*)d_in[3];   // scalar
    float* out          = (float*)d_out;           // [2,2048,32000]

    lowproj_kernel<<<NTOK / K1_TOKS, K1_TPB>>>(hidden, A, alpha);

    dim3 grid2((V4 + K2_THREADS - 1) / K2_THREADS,   // 32
               NTOK / T_TILE);                       // 64
    vocabproj_kernel<<<grid2, K2_THREADS>>>(B, out);
}

// round 15
// speedup vs baseline: 1.0131x; 1.0131x over previous
#include <cuda_runtime.h>
#include <cstdint>

// Problem constants
#define NBUCKETS 16
#define EMBD     1024
#define VOCAB    32000
#define SEQLEN   2048
#define RANK     8
#define BATCH    2
#define NTOK     (BATCH * SEQLEN)          // 4096 tokens
#define BUCKET_SHIFT 7                      // SEQLEN / NBUCKETS = 128 = 1<<7

#define TILE_TOKS 32                        // tokens per tile (32 | 128: one bucket)
#define NTILES    (NTOK / TILE_TOKS)        // 128 producer CTAs
#define NCHUNKS   32                        // vocab chunks of 256 float4
#define TPB       256
#define TGRP      4                         // tokens per butterfly group (producer)
#define NGRP      (TILE_TOKS / TGRP)        // 8 groups
#define V4        (VOCAB / 4)               // 8000

// Scratch + handoff state (zero-initialized device globals; no allocation)
__device__ float    g_low[NTOK * RANK];
__device__ unsigned g_flag[NTILES];
__device__ unsigned g_cnt[NTILES];

// ---------------------------------------------------------------------------
// Fused kernel with FAST producer (v6 register-A design).
//   bid <  NTILES : producer — low[tile] = alpha * hidden @ A[bucket]
//                   Register-resident A panel (8 float4/thread), pure
//                   LDG+FFMA main loop, butterfly reduce, 8KB smem combine.
//                   ~3-4us, releases per-tile flag.
//   bid >= NTILES : consumer — loads B panel first (independent), acquires
//                   its tile flag, then streams 32 token-rows of stores.
// Reads (hidden) now interleave with the write stream for the whole period,
// exploiting the higher mixed-stream DRAM throughput observed in R14.
// Last consumer of each tile resets flag/counter for graph-replay determinism.
// ---------------------------------------------------------------------------
__global__ __launch_bounds__(TPB, 4)
void fused_kernel(const float* __restrict__ hidden,
                  const float* __restrict__ A,
                  const float* __restrict__ B,
                  const float* __restrict__ alpha_p,
                  float* __restrict__ out)
{
    const int bid = blockIdx.x;
    const int tid = threadIdx.x;

    if (bid < NTILES) {
        // ================= PRODUCER (v6 style) =================
        __shared__ float part[8][TILE_TOKS][RANK];    // 8 KB warp partials

        const int tok0   = bid * TILE_TOKS;
        const int bucket = (tok0 & (SEQLEN - 1)) >> BUCKET_SHIFT;
        const float* __restrict__ Ab = A + (size_t)bucket * EMBD * RANK;

        const int wid  = tid >> 5;
        const int lane = tid & 31;
        const int e0   = tid * 4;                     // thread's 4 e-values

        // A panel in registers: af[k*8+r] = A[e0+k][r]
        float4 a[8];
#pragma unroll
        for (int j = 0; j < 8; j++)
            a[j] = *reinterpret_cast<const float4*>(Ab + (size_t)e0 * RANK + j * 4);
        const float* af = reinterpret_cast<const float*>(a);

        const float* __restrict__ hbase = hidden + (size_t)tok0 * EMBD + e0;

#pragma unroll
        for (int grp = 0; grp < NGRP; grp++) {
            // Batched hidden loads for 4 tokens (high MLP, coalesced 512B/warp).
            float4 hv[TGRP];
#pragma unroll
            for (int g = 0; g < TGRP; g++)
                hv[g] = __ldcs(reinterpret_cast<const float4*>(
                            hbase + (size_t)(grp * TGRP + g) * EMBD));
            const float* hf = reinterpret_cast<const float*>(hv); // hf[g*4+k]

            float v[TGRP * RANK];                    // acc i = g*8 + r
#pragma unroll
            for (int i = 0; i < TGRP * RANK; i++) v[i] = 0.0f;

#pragma unroll
            for (int k = 0; k < 4; k++) {
#pragma unroll
                for (int r = 0; r < RANK; r++) {
                    const float av = af[k * RANK + r];
#pragma unroll
                    for (int g = 0; g < TGRP; g++)
                        v[g * RANK + r] = fmaf(hf[g * 4 + k], av, v[g * RANK + r]);
                }
            }

            // Split-butterfly: 32 values over 32 lanes, 31 shuffles.
            // After: lane l holds the warp-sum for g = l>>3, r = l&7.
#pragma unroll
            for (int m = 16; m >= 1; m >>= 1) {
                const bool hi = (lane & m) != 0;
                const int h = m;
#pragma unroll
                for (int j = 0; j < 16; j++) {
                    if (j < h) {
                        float mine   = hi ? v[h + j] : v[j];
                        float theirs = hi ? v[j]     : v[h + j];
                        v[j] = mine + __shfl_xor_sync(0xFFFFFFFFu, theirs, m);
                    }
                }
            }

            part[wid][grp * TGRP + (lane >> 3)][lane & 7] = v[0];
        }
        __syncthreads();

        // Combine the 8 warps' e-slice partials; 256 threads cover 32 tok x 8 r.
        {
            const int tok = tid >> 3;
            const int r   = tid & 7;
            float s = 0.0f;
#pragma unroll
            for (int w = 0; w < 8; w++) s += part[w][tok][r];
            g_low[(size_t)(tok0 + tok) * RANK + r] = s * alpha_p[0];
        }

        // Publish.
        __threadfence();
        __syncthreads();
        if (tid == 0) {
            asm volatile("st.release.gpu.global.b32 [%0], %1;"
                         :: "l"(&g_flag[bid]), "r"(1u) : "memory");
        }
        return;
    }

    // ================= CONSUMER =================
    const int idx   = bid - NTILES;
    const int tile  = idx >> 5;          // / NCHUNKS
    const int chunk = idx & (NCHUNKS - 1);
    const int v4    = chunk * TPB + tid;
    const bool valid = (v4 < V4);
    const int vv    = v4 * 4;

    // Independent long-latency work first: B panel (8 rows x 4 cols).
    float4 b[RANK];
#pragma unroll
    for (int r = 0; r < RANK; r++) {
        if (valid)
            b[r] = *reinterpret_cast<const float4*>(B + (size_t)r * VOCAB + vv);
        else
            b[r] = make_float4(0.f, 0.f, 0.f, 0.f);
    }

    // Wait for this tile's producer.
    if (tid == 0) {
        unsigned f;
        do {
            asm volatile("ld.acquire.gpu.global.b32 %0, [%1];"
                         : "=r"(f) : "l"(&g_flag[tile]) : "memory");
            if (!f) __nanosleep(64);
        } while (!f);
    }
    __syncthreads();

    // Load tile's low values into shared (32 tok x 8 r = 64 float4).
    __shared__ float slow[TILE_TOKS * RANK];
    const int tok0 = tile * TILE_TOKS;
    if (tid < TILE_TOKS * RANK / 4) {
        reinterpret_cast<float4*>(slow)[tid] =
            reinterpret_cast<const float4*>(g_low + (size_t)tok0 * RANK)[tid];
    }
    __syncthreads();

    // Replay bookkeeping: last of the 32 consumers resets flag/counter.
    if (tid == 0) {
        unsigned old = atomicAdd(&g_cnt[tile], 1u);
        if (old == NCHUNKS - 1) {
            g_flag[tile] = 0u;
            g_cnt[tile]  = 0u;
        }
    }

    if (!valid) return;

    float* __restrict__ op = out + (size_t)tok0 * VOCAB + vv;

#pragma unroll 4
    for (int tt = 0; tt < TILE_TOKS; tt++) {
        const float* l = slow + tt * RANK;   // broadcast shared reads
        float4 o;
        o.x = l[0] * b[0].x; o.y = l[0] * b[0].y; o.z = l[0] * b[0].z; o.w = l[0] * b[0].w;
#pragma unroll
        for (int r = 1; r < RANK; r++) {
            o.x = fmaf(l[r], b[r].x, o.x);
            o.y = fmaf(l[r], b[r].y, o.y);
            o.z = fmaf(l[r], b[r].z, o.z);
            o.w = fmaf(l[r], b[r].w, o.w);
        }
        __stcs(reinterpret_cast<float4*>(op), o);   // streaming store (best measured)
        op += VOCAB;
    }
}

// ---------------------------------------------------------------------------
// Launch: producers occupy the lowest block ids (all dispatched in wave 1,
// no spin deadlock possible).
// ---------------------------------------------------------------------------
extern "C" void kernel_launch(void* const* d_in, const int* in_sizes, int n_in,
                              void* d_out, int out_size)
{
    const float* hidden = (const float*)d_in[0];   // [2,2048,1024]
    const float* A      = (const float*)d_in[1];   // [16,1024,8]
    const float* B      = (const float*)d_in[2];   // [8,32000]
    const float* alpha  = (const float*)d_in[3];   // scalar
    float* out          = (float*)d_out;           // [2,2048,32000]

    const int nblocks = NTILES + NTILES * NCHUNKS; // 128 + 4096 = 4224
    fused_kernel<<<nblocks, TPB>>>(hidden, A, B, alpha, out);
}